// round 17
// baseline (speedup 1.0000x reference)
#include <cuda_runtime.h>
#include <cuda_fp16.h>
#include <math.h>
#include <stdint.h>

// Problem dims (fixed by the dataset)
#define Bb 32
#define Ll 2048
#define Ee 1024
#define Uu 1024

// GEMM tiling (fp16 mma.sync m16n8k16), 2 CTAs/SM, 8 warps of 64x32
#define BM 128
#define BN 128
#define BKH 64                       // 64 halves per k-tile (128B data per row)
#define NKT (Ee / BKH)               // 16 k-tiles
#define ROWB 144                     // 128B data + 16B pad -> conflict-free ldmatrix
#define A_STAGE_BYTES (BM * ROWB)    // 18432
#define B_STAGE_BYTES (BN * ROWB)    // 18432
#define STAGE_BYTES (A_STAGE_BYTES + B_STAGE_BYTES)   // 36864
#define NSTAGE 3
#define SM_TILES_BYTES (NSTAGE * STAGE_BYTES)          // 110592
#define SM_BAR_OFF  (SM_TILES_BYTES)                   // 6 mbarriers (48B)
#define SM_BIAS_OFF (SM_BAR_OFF + 64)                  // 128 floats
#define SM_WC_OFF   (SM_BIAS_OFF + 512)
#define SM_V_OFF    (SM_WC_OFF + 512)
#define SM_ROW_OFF  (SM_V_OFF + 512)
#define SMEM_TOTAL  (SM_ROW_OFF + 512)                 // ~112.7KB (2/SM)

// prep_kernel block ranges — hW FIRST (starts at t=0, overlaps conv),
// then transpose, then the conv bulk.  (R16 proven form)
#define PREP_HW_BLOCKS   128
#define PREP_TR_BLOCKS   1024
#define PREP_CONV_BLOCKS 32768
#define PREP_HW_END   (PREP_HW_BLOCKS)
#define PREP_TR_END   (PREP_HW_BLOCKS + PREP_TR_BLOCKS)
#define PREP_GRID     (PREP_HW_BLOCKS + PREP_TR_BLOCKS + PREP_CONV_BLOCKS)

// Scratch (no cudaMalloc allowed)
__device__ float  g_score[Bb * Ll];
__device__ float  g_hW[Bb * Uu];
__device__ __half g_encH[(size_t)Bb * Ll * Ee];   // fp16 copy of enc (128MB)
__device__ __half g_WsTH[Uu * Ee];                // transposed Ws in fp16

// ---------------------------------------------------------------------------
__device__ __forceinline__ uint32_t smem_to_u32(const void* p) {
    uint32_t a;
    asm("{ .reg .u64 t; cvta.to.shared.u64 t, %1; cvt.u32.u64 %0, t; }" : "=r"(a) : "l"(p));
    return a;
}
__device__ __forceinline__ void cp16(uint32_t dst, const void* src) {
    asm volatile("cp.async.cg.shared.global [%0], [%1], 16;" :: "r"(dst), "l"(src) : "memory");
}
#define MBARRIER_INIT(mbar, count) \
    asm volatile("mbarrier.init.shared.b64 [%0], %1;" \
        :: "r"((uint32_t)(mbar)), "r"((uint32_t)(count)) : "memory")
#define MBARRIER_ARRIVE(mbar) \
    asm volatile("mbarrier.arrive.shared.b64 _, [%0];" :: "r"((uint32_t)(mbar)) : "memory")
#define CPASYNC_MBAR_ARRIVE(mbar) \
    asm volatile("cp.async.mbarrier.arrive.noinc.shared.b64 [%0];" \
        :: "r"((uint32_t)(mbar)) : "memory")
#define MBARRIER_WAIT_PARITY(mbar_smem_addr, phase_parity) do { \
    uint32_t _mbar = (uint32_t)(mbar_smem_addr); \
    uint32_t _parity = (uint32_t)(phase_parity); \
    uint32_t _done; \
    asm volatile("{\n\t.reg .pred p;\n\t" \
        "mbarrier.try_wait.parity.acquire.cta.shared::cta.b64 p, [%1], %2;\n\t" \
        "selp.b32 %0, 1, 0, p;\n\t}" : "=r"(_done) : "r"(_mbar), "r"(_parity) : "memory"); \
    if (!_done) { \
        asm volatile("{\n\t.reg .pred P1;\n\t" \
            "WAIT_LOOP_%=:\n\t" \
            "mbarrier.try_wait.parity.acquire.cta.shared::cta.b64 P1, [%0], %1, 0x989680;\n\t" \
            "@P1 bra.uni WAIT_DONE_%=;\n\t" \
            "bra.uni WAIT_LOOP_%=;\n\t" \
            "WAIT_DONE_%=:\n\t}" :: "r"(_mbar), "r"(_parity) : "memory"); \
    } \
} while (0)

__device__ __forceinline__ void ldsm4(unsigned& r0, unsigned& r1, unsigned& r2,
                                      unsigned& r3, uint32_t addr) {
    asm volatile("ldmatrix.sync.aligned.m8n8.x4.shared.b16 {%0,%1,%2,%3}, [%4];"
                 : "=r"(r0), "=r"(r1), "=r"(r2), "=r"(r3) : "r"(addr));
}

__device__ __forceinline__ void mma16(float d[4], const unsigned a[4], const unsigned b[2]) {
    asm volatile(
        "mma.sync.aligned.m16n8k16.row.col.f32.f16.f16.f32 "
        "{%0,%1,%2,%3},{%4,%5,%6,%7},{%8,%9},{%0,%1,%2,%3};"
        : "+f"(d[0]), "+f"(d[1]), "+f"(d[2]), "+f"(d[3])
        : "r"(a[0]), "r"(a[1]), "r"(a[2]), "r"(a[3]), "r"(b[0]), "r"(b[1]));
}

// HW tanh approximation (MUFU.TANH, sm_75+): 1 MUFU op, |err| ~5e-4
__device__ __forceinline__ float fast_tanh(float x) {
    float y;
    asm("tanh.approx.f32 %0, %1;" : "=f"(y) : "f"(x));
    return y;
}

// ---------------------------------------------------------------------------
// prep_kernel: fused prologue (R16 proven form: hW first, then transpose,
// then the conv bulk).
// ---------------------------------------------------------------------------
__global__ void __launch_bounds__(256)
prep_kernel(const float* __restrict__ enc,
            const float* __restrict__ Ws,
            const float* __restrict__ dec,
            const float* __restrict__ Wh,
            const float* __restrict__ Wsb,
            const float* __restrict__ Whb,
            const float* __restrict__ Wcb,
            const int* __restrict__ ucp,
            float* __restrict__ ctx) {
    __shared__ float sbuf[1056];
    const int bid = blockIdx.x;
    const int tid = threadIdx.x;

    if (bid < PREP_HW_END) {
        // ---- hW + zero score/ctx (runs first, overlaps conv) ----
        const int t = bid;                        // 0..127
        const int uSlice = t & 3;
        const int b = t >> 2;
        const int u = uSlice * 256 + tid;

        for (int e = tid; e < Ee; e += 256) sbuf[e] = dec[b * Ee + e];
        __syncthreads();

        float acc = 0.f;
#pragma unroll 8
        for (int e = 0; e < Ee; e++) acc += sbuf[e] * Wh[(size_t)e * Uu + u];

        const int uc = *ucp;
        g_hW[b * Uu + u] = acc + Wsb[u] + Whb[u] + (uc ? Wcb[u] : 0.f);

        const int idx = t * 256 + tid;   // 0..32767
        g_score[idx * 2 + 0] = 0.f;
        g_score[idx * 2 + 1] = 0.f;
        ctx[idx] = 0.f;
    } else if (bid < PREP_TR_END) {
        // ---- Ws transpose -> fp16 ----
        const int t  = bid - PREP_HW_END;
        const int bx = t & 31, by = t >> 5;
        const int tx = tid & 31, ty = tid >> 5;   // (32, 8)
#pragma unroll
        for (int j = 0; j < 4; j++)
            sbuf[(ty + j * 8) * 33 + tx] =
                Ws[(size_t)(by * 32 + ty + j * 8) * Uu + bx * 32 + tx];
        __syncthreads();
#pragma unroll
        for (int j = 0; j < 4; j++)
            g_WsTH[(size_t)(bx * 32 + ty + j * 8) * Ee + by * 32 + tx] =
                __float2half_rn(sbuf[tx * 33 + (ty + j * 8)]);
    } else {
        // ---- enc -> fp16 (bulk) ----
        const int t = bid - PREP_TR_END;
        const size_t i = ((size_t)t * 256 + tid) * 8;
        const float4 v0 = *(const float4*)(enc + i);
        const float4 v1 = *(const float4*)(enc + i + 4);
        __half2 h0 = __floats2half2_rn(v0.x, v0.y);
        __half2 h1 = __floats2half2_rn(v0.z, v0.w);
        __half2 h2 = __floats2half2_rn(v1.x, v1.y);
        __half2 h3 = __floats2half2_rn(v1.z, v1.w);
        uint4 o;
        o.x = *(uint32_t*)&h0; o.y = *(uint32_t*)&h1;
        o.z = *(uint32_t*)&h2; o.w = *(uint32_t*)&h3;
        *(uint4*)(g_encH + i) = o;
    }
}

// ---------------------------------------------------------------------------
// Kernel 2: fp16 mma.sync GEMM (128x128 block, 8 warps of 64x32, 2 CTAs/SM)
// + fused tanh/V epilogue -> score. 256 threads, 3-stage mbarrier pipeline.
// (FROZEN: R12 form — measured best across 4 attempted restructures)
// ---------------------------------------------------------------------------
__device__ __forceinline__ void stage_tile(uint32_t smBase, int buf,
                                           const __half* __restrict__ aG,
                                           const __half* __restrict__ bG,
                                           int kt, int tid) {
    const uint32_t st = smBase + buf * STAGE_BYTES;
#pragma unroll
    for (int i = 0; i < 4; i++) {
        const int c = tid + i * 256;
        const int r = c >> 3, ch = c & 7;
        cp16(st + r * ROWB + ch * 16, aG + (size_t)r * Ee + kt * BKH + ch * 8);
    }
    const uint32_t bO = st + A_STAGE_BYTES;
#pragma unroll
    for (int i = 0; i < 4; i++) {
        const int c = tid + i * 256;
        const int r = c >> 3, ch = c & 7;
        cp16(bO + r * ROWB + ch * 16, bG + (size_t)r * Ee + kt * BKH + ch * 8);
    }
}

__global__ void __launch_bounds__(256, 2)
gemm_score_h(const float* __restrict__ Wc,
             const float* __restrict__ Vk,
             const float* __restrict__ cov,
             const int* __restrict__ ucp) {
    extern __shared__ char smem[];
    const uint32_t smBase = smem_to_u32(smem);
    const int tid  = threadIdx.x;
    const int wid  = tid >> 5;
    const int lane = tid & 31;
    const int g    = lane >> 2;
    const int tig  = lane & 3;
    const int wm   = wid >> 2;     // 0..1 (M)
    const int wn   = wid & 3;      // 0..3 (N)

    const int rowBase = blockIdx.y * BM;
    const int colBase = blockIdx.x * BN;
    const int b = rowBase >> 11;
    const int uc = *ucp;

    const uint32_t fullB  = smBase + SM_BAR_OFF;
    const uint32_t emptyB = smBase + SM_BAR_OFF + 24;

    float* sBias = (float*)(smem + SM_BIAS_OFF);
    float* sWc   = (float*)(smem + SM_WC_OFF);
    float* sV    = (float*)(smem + SM_V_OFF);
    float* sRow  = (float*)(smem + SM_ROW_OFF);

    if (tid < 128) {
        const int u = colBase + tid;
        sBias[tid] = g_hW[b * Uu + u];
        sWc[tid]   = uc ? Wc[u] : 0.f;
        sV[tid]    = Vk[u];
        sRow[tid]  = 0.f;
    }
    if (tid < NSTAGE) {
        MBARRIER_INIT(fullB + tid * 8, 256);
        MBARRIER_INIT(emptyB + tid * 8, 256);
    }
    __syncthreads();   // barriers + constants visible; the ONLY block barrier

    const __half* aG = g_encH + (size_t)rowBase * Ee;
    const __half* bG = g_WsTH + (size_t)colBase * Ee;

    const uint32_t aLane = (uint32_t)((lane & 15) * ROWB + (lane >> 4) * 16);
    const uint32_t bLane = (uint32_t)((((lane >> 4) << 3) + (lane & 7)) * ROWB
                                      + ((lane >> 3) & 1) * 16);

    // producer cursor: starts phase 1 (first empty-waits pass immediately)
    int pStage = 0, pPhase = 1;
    // consumer cursor
    int cStage = 0, cPhase = 0;

    // prologue: stage k-tiles 0 and 1 into stages 0,1
#pragma unroll
    for (int k0 = 0; k0 < 2; k0++) {
        MBARRIER_WAIT_PARITY(emptyB + pStage * 8, pPhase);
        stage_tile(smBase, pStage, aG, bG, k0, tid);
        CPASYNC_MBAR_ARRIVE(fullB + pStage * 8);
        if (++pStage == NSTAGE) { pStage = 0; pPhase ^= 1; }
    }

    float acc[4][4][4];
#pragma unroll
    for (int i = 0; i < 4; i++)
#pragma unroll
        for (int j = 0; j < 4; j++)
#pragma unroll
            for (int k = 0; k < 4; k++) acc[i][j][k] = 0.f;

    for (int kt = 0; kt < NKT; kt++) {
        // produce stage for kt+2
        if (kt + 2 < NKT) {
            MBARRIER_WAIT_PARITY(emptyB + pStage * 8, pPhase);
            stage_tile(smBase, pStage, aG, bG, kt + 2, tid);
            CPASYNC_MBAR_ARRIVE(fullB + pStage * 8);
            if (++pStage == NSTAGE) { pStage = 0; pPhase ^= 1; }
        }

        // consume stage for kt
        MBARRIER_WAIT_PARITY(fullB + cStage * 8, cPhase);

        const uint32_t sA = smBase + cStage * STAGE_BYTES;
        const uint32_t sB = sA + A_STAGE_BYTES;
        const uint32_t aBase = sA + (wm * 64) * ROWB + aLane;
        const uint32_t bBase = sB + (wn * 32) * ROWB + bLane;

        unsigned af[2][4][4];
        unsigned bf[4][2];

#pragma unroll
        for (int mi = 0; mi < 4; mi++)
            ldsm4(af[0][mi][0], af[0][mi][1], af[0][mi][2], af[0][mi][3],
                  aBase + mi * 16 * ROWB);

#pragma unroll
        for (int s = 0; s < 4; s++) {
#pragma unroll
            for (int p = 0; p < 2; p++) {
                unsigned r0, r1, r2, r3;
                ldsm4(r0, r1, r2, r3, bBase + p * 16 * ROWB + s * 32);
                bf[2 * p][0] = r0;     bf[2 * p][1] = r1;
                bf[2 * p + 1][0] = r2; bf[2 * p + 1][1] = r3;
            }
            if (s < 3) {
#pragma unroll
                for (int mi = 0; mi < 4; mi++)
                    ldsm4(af[(s + 1) & 1][mi][0], af[(s + 1) & 1][mi][1],
                          af[(s + 1) & 1][mi][2], af[(s + 1) & 1][mi][3],
                          aBase + mi * 16 * ROWB + (s + 1) * 32);
            }
#pragma unroll
            for (int mi = 0; mi < 4; mi++)
#pragma unroll
                for (int ni = 0; ni < 4; ni++)
                    mma16(acc[mi][ni], af[s & 1][mi], bf[ni]);
        }

        // all LDSMs for this stage executed -> release it
        MBARRIER_ARRIVE(emptyB + cStage * 8);
        if (++cStage == NSTAGE) { cStage = 0; cPhase ^= 1; }
    }

    // ---------------- fused epilogue ----------------
#pragma unroll
    for (int mi = 0; mi < 4; mi++) {
        const int r0 = wm * 64 + mi * 16 + g;
        const int r1 = r0 + 8;
        const float cv0 = uc ? cov[rowBase + r0] : 0.f;
        const float cv1 = uc ? cov[rowBase + r1] : 0.f;
        float s0 = 0.f, s1 = 0.f;
#pragma unroll
        for (int ni = 0; ni < 4; ni++) {
            const int c0 = wn * 32 + ni * 8 + 2 * tig;
            const int c1 = c0 + 1;
            const float b0 = sBias[c0], b1 = sBias[c1];
            const float w0 = sWc[c0],  w1 = sWc[c1];
            const float v0 = sV[c0],   v1 = sV[c1];
            s0 += fast_tanh(acc[mi][ni][0] + b0 + cv0 * w0) * v0
                + fast_tanh(acc[mi][ni][1] + b1 + cv0 * w1) * v1;
            s1 += fast_tanh(acc[mi][ni][2] + b0 + cv1 * w0) * v0
                + fast_tanh(acc[mi][ni][3] + b1 + cv1 * w1) * v1;
        }
        s0 += __shfl_xor_sync(0xFFFFFFFFu, s0, 1);
        s0 += __shfl_xor_sync(0xFFFFFFFFu, s0, 2);
        s1 += __shfl_xor_sync(0xFFFFFFFFu, s1, 1);
        s1 += __shfl_xor_sync(0xFFFFFFFFu, s1, 2);
        if (tig == 0) {
            atomicAdd(&sRow[r0], s0);
            atomicAdd(&sRow[r1], s1);
        }
    }
    __syncthreads();
    if (tid < 128) atomicAdd(&g_score[rowBase + tid], sRow[tid]);
}

// ---------------------------------------------------------------------------
// Kernel 3: masked softmax over L per batch; writes attn and coverage outputs
// ---------------------------------------------------------------------------
__global__ void softmax_kernel(const float* __restrict__ cov,
                               const float* __restrict__ Vb,
                               const int* __restrict__ mask,
                               const int* __restrict__ ucp,
                               float* __restrict__ attn,
                               float* __restrict__ covOut) {
    __shared__ float red[256];
    const int b = blockIdx.x;
    const int tid = threadIdx.x;
    const float vb = Vb[0];
    const int uc = *ucp;

    float vals[8];
    float mx = -INFINITY;
#pragma unroll
    for (int i = 0; i < 8; i++) {
        const int l = tid + i * 256;
        const float s = (g_score[b * Ll + l] + vb) * (float)mask[b * Ll + l];
        vals[i] = s;
        mx = fmaxf(mx, s);
    }
    red[tid] = mx;
    __syncthreads();
    for (int s = 128; s > 0; s >>= 1) {
        if (tid < s) red[tid] = fmaxf(red[tid], red[tid + s]);
        __syncthreads();
    }
    mx = red[0];
    __syncthreads();

    float sum = 0.f;
#pragma unroll
    for (int i = 0; i < 8; i++) {
        vals[i] = __expf(vals[i] - mx);
        sum += vals[i];
    }
    red[tid] = sum;
    __syncthreads();
    for (int s = 128; s > 0; s >>= 1) {
        if (tid < s) red[tid] += red[tid + s];
        __syncthreads();
    }
    const float inv = 1.f / red[0];

#pragma unroll
    for (int i = 0; i < 8; i++) {
        const int l = tid + i * 256;
        const float w = vals[i] * inv;
        attn[b * Ll + l] = w;
        covOut[b * Ll + l] = w + (uc ? cov[b * Ll + l] : 0.f);
    }
}

// ---------------------------------------------------------------------------
// Kernel 4: context[b,e] += sum_{l in chunk} attn[b,l] * encH[b,l,e]
// grid (16, 32), 256 threads. 128-row chunks; block split into two 128-thread
// row groups; uint4 (8-half) loads per thread. Atomics into pre-zeroed ctx.
// ---------------------------------------------------------------------------
__global__ void __launch_bounds__(256)
context_kernel(const float* __restrict__ attn,
               float* __restrict__ ctx) {
    __shared__ float w[128];
    const int b = blockIdx.y;
    const int l0 = blockIdx.x * 128;
    if (threadIdx.x < 128) w[threadIdx.x] = attn[b * Ll + l0 + threadIdx.x];
    __syncthreads();

    const int half = threadIdx.x >> 7;     // 0/1: row sub-range (64 rows each)
    const int e8   = threadIdx.x & 127;    // 8-half e-chunk
    // row stride = Ee halves = 128 uint4
    const uint4* ep = (const uint4*)(g_encH + ((size_t)b * Ll + l0 + half * 64) * Ee) + e8;

    float acc[8];
#pragma unroll
    for (int i = 0; i < 8; i++) acc[i] = 0.f;

#pragma unroll 4
    for (int l = 0; l < 64; l++) {
        const float wv = w[half * 64 + l];
        const uint4 raw = ep[(size_t)l * 128];
        const float2 f0 = __half22float2(*(const __half2*)&raw.x);
        const float2 f1 = __half22float2(*(const __half2*)&raw.y);
        const float2 f2 = __half22float2(*(const __half2*)&raw.z);
        const float2 f3 = __half22float2(*(const __half2*)&raw.w);
        acc[0] += wv * f0.x; acc[1] += wv * f0.y;
        acc[2] += wv * f1.x; acc[3] += wv * f1.y;
        acc[4] += wv * f2.x; acc[5] += wv * f2.y;
        acc[6] += wv * f3.x; acc[7] += wv * f3.y;
    }

    float* c = ctx + b * Ee + e8 * 8;
#pragma unroll
    for (int i = 0; i < 8; i++) atomicAdd(c + i, acc[i]);
}

// ---------------------------------------------------------------------------
extern "C" void kernel_launch(void* const* d_in, const int* in_sizes, int n_in,
                              void* d_out, int out_size) {
    const float* dec  = (const float*)d_in[0];
    const float* enc  = (const float*)d_in[1];
    const float* cov  = (const float*)d_in[2];
    const float* Wsk  = (const float*)d_in[3];
    const float* Wsb  = (const float*)d_in[4];
    const float* Whk  = (const float*)d_in[5];
    const float* Whb  = (const float*)d_in[6];
    const float* Wck  = (const float*)d_in[7];
    const float* Wcb  = (const float*)d_in[8];
    const float* Vk   = (const float*)d_in[9];
    const float* Vb   = (const float*)d_in[10];
    const int*   mask = (const int*)d_in[11];
    const int*   ucp  = (const int*)d_in[12];

    float* out    = (float*)d_out;
    float* ctx    = out;                       // [32, 1024]
    float* attn   = out + Bb * Ee;             // [32, 2048]
    float* covOut = attn + Bb * Ll;            // [32, 2048]

    cudaFuncSetAttribute(gemm_score_h, cudaFuncAttributeMaxDynamicSharedMemorySize,
                         SMEM_TOTAL);

    prep_kernel<<<PREP_GRID, 256>>>(enc, Wsk, dec, Whk, Wsb, Whb, Wcb, ucp, ctx);
    gemm_score_h<<<dim3(Uu / BN, (Bb * Ll) / BM), 256, SMEM_TOTAL>>>(Wck, Vk, cov, ucp);
    softmax_kernel<<<Bb, 256>>>(cov, Vb, mask, ucp, attn, covOut);
    context_kernel<<<dim3(16, Bb), 256>>>(attn, ctx);
}